// round 10
// baseline (speedup 1.0000x reference)
#include <cuda_runtime.h>
#include <cuda_fp16.h>
#include <cstdint>

// Bidirectional LSTM (H=128, I=4, B=256, T=512), final h only. out [B,2H] fp32.
// Grid: 128 CTAs = 2 dirs x 64 batch-tiles (BT=4), 256 threads (8 warps).
// Weight-stationary register MMA: warp w holds Whh rows [w*64,(w+1)*64) as
// m16n8k16 A fragments in registers (loaded once). Per step:
//   gates[512,8] = Whh_fp16 @ h_fp16^T  (N=8: batches 0-3 real, 4-7 zero)
// via 4 m-tiles x 8 k-chunks of mma.sync.m16n8k16.f32.f16.f16.f32 per warp.
// Epilogue: thread u owns unit j=u&127, batches 2bp,2bp+1 (bp=u>>7); fp32 xw,
// accurate exp-based activations, fp32 c/h; h -> fp16 -> B buffer in SMEM.

#define HD     128
#define TLEN   512
#define BT     4
#define NTH    256
#define GPITCH 10        // gates row pitch in floats (40 B)
#define HPITCH 136       // h row pitch in halves (272 B, conflict-free)

// dynamic SMEM layout (bytes)
#define SM_GATES  0
#define GATES_B   (512 * GPITCH * 4)            // 20480
#define SM_H      GATES_B                        // 20480
#define H_B       (8 * HPITCH * 2)               // 2176
#define SM_X      (SM_GATES + GATES_B + H_B)     // 22656
#define X_B       (TLEN * BT * 4 * 4)            // 32768
#define SM_TOTAL  (SM_X + X_B)                   // 55424

__device__ __forceinline__ void mma16816(float* d, const uint32_t* a,
                                         uint32_t b0, uint32_t b1) {
    asm volatile(
        "mma.sync.aligned.m16n8k16.row.col.f32.f16.f16.f32 "
        "{%0,%1,%2,%3}, {%4,%5,%6,%7}, {%8,%9}, {%0,%1,%2,%3};"
        : "+f"(d[0]), "+f"(d[1]), "+f"(d[2]), "+f"(d[3])
        : "r"(a[0]), "r"(a[1]), "r"(a[2]), "r"(a[3]), "r"(b0), "r"(b1));
}

__device__ __forceinline__ uint32_t packh2(float lo, float hi) {
    __half2 h = __floats2half2_rn(lo, hi);
    return *reinterpret_cast<uint32_t*>(&h);
}
__device__ __forceinline__ float sigmoid_f(float x) {
    float e = __expf(-x);
    return __fdividef(1.0f, 1.0f + e);
}
__device__ __forceinline__ float tanh_f(float x) {
    float ax = fabsf(x);
    float e = __expf(-2.0f * ax);
    float t = __fdividef(1.0f - e, 1.0f + e);
    return copysignf(t, x);
}

__global__ void __launch_bounds__(NTH, 1)
lstm_mma_kernel(const float* __restrict__ x,
                const float* __restrict__ Wih_f, const float* __restrict__ Whh_f,
                const float* __restrict__ bih_f, const float* __restrict__ bhh_f,
                const float* __restrict__ Wih_b, const float* __restrict__ Whh_b,
                const float* __restrict__ bih_b, const float* __restrict__ bhh_b,
                float* __restrict__ out)
{
    extern __shared__ unsigned char smem[];
    float*  gates_sm = reinterpret_cast<float*>(smem + SM_GATES);
    __half* h_sm     = reinterpret_cast<__half*>(smem + SM_H);
    float*  x_sm     = reinterpret_cast<float*>(smem + SM_X);

    const int tid = threadIdx.x;
    const int w   = tid >> 5;          // warp 0..7
    const int l   = tid & 31;
    const int gid = l >> 2;            // 0..7
    const int tig = l & 3;             // 0..3
    const int bx  = blockIdx.x;
    const int dir = bx >> 6;
    const int b_base = (bx & 63) * BT;

    const float* Wih = dir ? Wih_b : Wih_f;
    const float* Whh = dir ? Whh_b : Whh_f;
    const float* bih = dir ? bih_b : bih_f;
    const float* bhh = dir ? bhh_b : bhh_f;

    // ---- Load stationary A fragments: warp w owns rows [w*64, w*64+64) ----
    // a[mt][kc][0..3]: rows (r0, r0+8) x k (k0,k0+1, k0+8,k0+9), r0=w*64+mt*16+gid
    uint32_t A[4][8][4];
    #pragma unroll
    for (int mt = 0; mt < 4; mt++) {
        const int r0 = w * 64 + mt * 16 + gid;
        const float* row0 = Whh + r0 * HD;
        const float* row1 = Whh + (r0 + 8) * HD;
        #pragma unroll
        for (int kc = 0; kc < 8; kc++) {
            const int k0 = kc * 16 + tig * 2;
            float2 p00 = *reinterpret_cast<const float2*>(row0 + k0);
            float2 p10 = *reinterpret_cast<const float2*>(row1 + k0);
            float2 p01 = *reinterpret_cast<const float2*>(row0 + k0 + 8);
            float2 p11 = *reinterpret_cast<const float2*>(row1 + k0 + 8);
            A[mt][kc][0] = packh2(p00.x, p00.y);
            A[mt][kc][1] = packh2(p10.x, p10.y);
            A[mt][kc][2] = packh2(p01.x, p01.y);
            A[mt][kc][3] = packh2(p11.x, p11.y);
        }
    }

    // ---- Zero h buffer (8 rows x HPITCH halves; rows 4-7 stay zero) ----
    for (int i = tid; i < (8 * HPITCH) / 2; i += NTH)
        reinterpret_cast<uint32_t*>(h_sm)[i] = 0u;

    // ---- Stage x slice: x_sm[t][b][i] ----
    for (int idx = tid; idx < BT * TLEN * 4; idx += NTH) {
        int b = idx >> 11, r = idx & 2047;
        x_sm[(r >> 2) * (BT * 4) + b * 4 + (r & 3)] = x[(b_base + b) * (TLEN * 4) + r];
    }

    // ---- Epilogue constants: thread u owns unit j, batches 2bp, 2bp+1 ----
    const int j  = tid & 127;
    const int bp = tid >> 7;
    float4 wi[4];
    float  bias[4];
    #pragma unroll
    for (int gt = 0; gt < 4; gt++) {
        int g = gt * 128 + j;
        wi[gt]   = *reinterpret_cast<const float4*>(Wih + g * 4);
        bias[gt] = bih[g] + bhh[g];
    }
    float cA = 0.f, cB = 0.f, hA = 0.f, hB = 0.f;

    const __half* hrow = h_sm + gid * HPITCH + tig * 2;   // B frag base (n=gid)
    __syncthreads();

    for (int t = 0; t < TLEN; t++) {
        const int tx = dir ? (TLEN - 1 - t) : t;

        // ---- B fragments from h_sm ----
        uint32_t b0[8], b1[8];
        #pragma unroll
        for (int kc = 0; kc < 8; kc++) {
            b0[kc] = *reinterpret_cast<const uint32_t*>(hrow + kc * 16);
            b1[kc] = *reinterpret_cast<const uint32_t*>(hrow + kc * 16 + 8);
        }

        // ---- MMA: 4 m-tiles x 8 k-chunks ----
        float acc[4][4];
        #pragma unroll
        for (int mt = 0; mt < 4; mt++) {
            acc[mt][0] = acc[mt][1] = acc[mt][2] = acc[mt][3] = 0.f;
            #pragma unroll
            for (int kc = 0; kc < 8; kc++)
                mma16816(acc[mt], A[mt][kc], b0[kc], b1[kc]);
        }

        // ---- Dump gates (cols 0-3 live in lanes tig<2) ----
        if (tig < 2) {
            #pragma unroll
            for (int mt = 0; mt < 4; mt++) {
                const int r0 = w * 64 + mt * 16 + gid;
                *reinterpret_cast<float2*>(gates_sm + r0 * GPITCH + tig * 2) =
                    make_float2(acc[mt][0], acc[mt][1]);
                *reinterpret_cast<float2*>(gates_sm + (r0 + 8) * GPITCH + tig * 2) =
                    make_float2(acc[mt][2], acc[mt][3]);
            }
        }
        __syncthreads();

        // ---- Epilogue: unit j, batches 2bp, 2bp+1 ----
        float2 gi = *reinterpret_cast<const float2*>(gates_sm + (0 * 128 + j) * GPITCH + bp * 2);
        float2 gf = *reinterpret_cast<const float2*>(gates_sm + (1 * 128 + j) * GPITCH + bp * 2);
        float2 gg = *reinterpret_cast<const float2*>(gates_sm + (2 * 128 + j) * GPITCH + bp * 2);
        float2 go = *reinterpret_cast<const float2*>(gates_sm + (3 * 128 + j) * GPITCH + bp * 2);

        const float* xr = x_sm + tx * (BT * 4) + bp * 8;
        float4 xa = *reinterpret_cast<const float4*>(xr);
        float4 xb = *reinterpret_cast<const float4*>(xr + 4);

        #pragma unroll
        for (int gt = 0; gt < 4; gt++) {
            float xwA = fmaf(xa.x, wi[gt].x, fmaf(xa.y, wi[gt].y,
                        fmaf(xa.z, wi[gt].z, fmaf(xa.w, wi[gt].w, bias[gt]))));
            float xwB = fmaf(xb.x, wi[gt].x, fmaf(xb.y, wi[gt].y,
                        fmaf(xb.z, wi[gt].z, fmaf(xb.w, wi[gt].w, bias[gt]))));
            if (gt == 0) { gi.x += xwA; gi.y += xwB; }
            if (gt == 1) { gf.x += xwA; gf.y += xwB; }
            if (gt == 2) { gg.x += xwA; gg.y += xwB; }
            if (gt == 3) { go.x += xwA; go.y += xwB; }
        }

        {
            float iv = sigmoid_f(gi.x), fv = sigmoid_f(gf.x);
            float gv = tanh_f(gg.x),    ov = sigmoid_f(go.x);
            cA = fmaf(fv, cA, iv * gv); hA = ov * tanh_f(cA);
        }
        {
            float iv = sigmoid_f(gi.y), fv = sigmoid_f(gf.y);
            float gv = tanh_f(gg.y),    ov = sigmoid_f(go.y);
            cB = fmaf(fv, cB, iv * gv); hB = ov * tanh_f(cB);
        }
        h_sm[(bp * 2 + 0) * HPITCH + j] = __float2half_rn(hA);
        h_sm[(bp * 2 + 1) * HPITCH + j] = __float2half_rn(hB);
        __syncthreads();
    }

    // ---- Output: out[b][dir*128 + j], fp32 from registers ----
    out[(b_base + bp * 2 + 0) * (2 * HD) + dir * HD + j] = hA;
    out[(b_base + bp * 2 + 1) * (2 * HD) + dir * HD + j] = hB;
}

extern "C" void kernel_launch(void* const* d_in, const int* in_sizes, int n_in,
                              void* d_out, int out_size)
{
    const float* x     = (const float*)d_in[0];
    const float* Wih_f = (const float*)d_in[1];
    const float* Whh_f = (const float*)d_in[2];
    const float* bih_f = (const float*)d_in[3];
    const float* bhh_f = (const float*)d_in[4];
    const float* Wih_b = (const float*)d_in[5];
    const float* Whh_b = (const float*)d_in[6];
    const float* bih_b = (const float*)d_in[7];
    const float* bhh_b = (const float*)d_in[8];
    float* out = (float*)d_out;

    cudaFuncSetAttribute(lstm_mma_kernel,
                         cudaFuncAttributeMaxDynamicSharedMemorySize, SM_TOTAL);

    lstm_mma_kernel<<<128, NTH, SM_TOTAL>>>(
        x, Wih_f, Whh_f, bih_f, bhh_f, Wih_b, Whh_b, bih_b, bhh_b, out);
}

// round 11
// speedup vs baseline: 1.0060x; 1.0060x over previous
#include <cuda_runtime.h>
#include <cuda_fp16.h>
#include <cstdint>

// Bidirectional LSTM (H=128, I=4, B=256, T=512), final h only. out [B,2H] fp32.
// Grid: 128 CTAs = 2 dirs x 64 batch-tiles (BT=4), 256 threads (8 warps).
// Weight-stationary register MMA: warp w holds Whh rows [w*64,(w+1)*64) as
// m16n8k16 A fragments in registers (loaded once). Per step:
//   gates[512,8] = Whh_fp16 @ h_fp16^T  (N=8: batches 0-3 real, 4-7 zero)
// via 4 m-tiles x 8 k-chunks of mma.sync.m16n8k16.f32.f16.f16.f32 per warp.
// Epilogue: thread u owns unit j=u&127, batches 2bp,2bp+1 (bp=u>>7); fp32 xw,
// accurate exp-based activations, fp32 c/h; h -> fp16 -> B buffer in SMEM.

#define HD     128
#define TLEN   512
#define BT     4
#define NTH    256
#define GPITCH 10        // gates row pitch in floats (40 B)
#define HPITCH 136       // h row pitch in halves (272 B, conflict-free)

// dynamic SMEM layout (bytes)
#define SM_GATES  0
#define GATES_B   (512 * GPITCH * 4)            // 20480
#define SM_H      GATES_B                        // 20480
#define H_B       (8 * HPITCH * 2)               // 2176
#define SM_X      (SM_GATES + GATES_B + H_B)     // 22656
#define X_B       (TLEN * BT * 4 * 4)            // 32768
#define SM_TOTAL  (SM_X + X_B)                   // 55424

__device__ __forceinline__ void mma16816(float* d, const uint32_t* a,
                                         uint32_t b0, uint32_t b1) {
    asm volatile(
        "mma.sync.aligned.m16n8k16.row.col.f32.f16.f16.f32 "
        "{%0,%1,%2,%3}, {%4,%5,%6,%7}, {%8,%9}, {%0,%1,%2,%3};"
        : "+f"(d[0]), "+f"(d[1]), "+f"(d[2]), "+f"(d[3])
        : "r"(a[0]), "r"(a[1]), "r"(a[2]), "r"(a[3]), "r"(b0), "r"(b1));
}

__device__ __forceinline__ uint32_t packh2(float lo, float hi) {
    __half2 h = __floats2half2_rn(lo, hi);
    return *reinterpret_cast<uint32_t*>(&h);
}
__device__ __forceinline__ float sigmoid_f(float x) {
    float e = __expf(-x);
    return __fdividef(1.0f, 1.0f + e);
}
__device__ __forceinline__ float tanh_f(float x) {
    float ax = fabsf(x);
    float e = __expf(-2.0f * ax);
    float t = __fdividef(1.0f - e, 1.0f + e);
    return copysignf(t, x);
}

__global__ void __launch_bounds__(NTH, 1)
lstm_mma_kernel(const float* __restrict__ x,
                const float* __restrict__ Wih_f, const float* __restrict__ Whh_f,
                const float* __restrict__ bih_f, const float* __restrict__ bhh_f,
                const float* __restrict__ Wih_b, const float* __restrict__ Whh_b,
                const float* __restrict__ bih_b, const float* __restrict__ bhh_b,
                float* __restrict__ out)
{
    extern __shared__ unsigned char smem[];
    float*  gates_sm = reinterpret_cast<float*>(smem + SM_GATES);
    __half* h_sm     = reinterpret_cast<__half*>(smem + SM_H);
    float*  x_sm     = reinterpret_cast<float*>(smem + SM_X);

    const int tid = threadIdx.x;
    const int w   = tid >> 5;          // warp 0..7
    const int l   = tid & 31;
    const int gid = l >> 2;            // 0..7
    const int tig = l & 3;             // 0..3
    const int bx  = blockIdx.x;
    const int dir = bx >> 6;
    const int b_base = (bx & 63) * BT;

    const float* Wih = dir ? Wih_b : Wih_f;
    const float* Whh = dir ? Whh_b : Whh_f;
    const float* bih = dir ? bih_b : bih_f;
    const float* bhh = dir ? bhh_b : bhh_f;

    // ---- Load stationary A fragments: warp w owns rows [w*64, w*64+64) ----
    // a[mt][kc][0..3]: rows (r0, r0+8) x k (k0,k0+1, k0+8,k0+9), r0=w*64+mt*16+gid
    uint32_t A[4][8][4];
    #pragma unroll
    for (int mt = 0; mt < 4; mt++) {
        const int r0 = w * 64 + mt * 16 + gid;
        const float* row0 = Whh + r0 * HD;
        const float* row1 = Whh + (r0 + 8) * HD;
        #pragma unroll
        for (int kc = 0; kc < 8; kc++) {
            const int k0 = kc * 16 + tig * 2;
            float2 p00 = *reinterpret_cast<const float2*>(row0 + k0);
            float2 p10 = *reinterpret_cast<const float2*>(row1 + k0);
            float2 p01 = *reinterpret_cast<const float2*>(row0 + k0 + 8);
            float2 p11 = *reinterpret_cast<const float2*>(row1 + k0 + 8);
            A[mt][kc][0] = packh2(p00.x, p00.y);
            A[mt][kc][1] = packh2(p10.x, p10.y);
            A[mt][kc][2] = packh2(p01.x, p01.y);
            A[mt][kc][3] = packh2(p11.x, p11.y);
        }
    }

    // ---- Zero h buffer (8 rows x HPITCH halves; rows 4-7 stay zero) ----
    for (int i = tid; i < (8 * HPITCH) / 2; i += NTH)
        reinterpret_cast<uint32_t*>(h_sm)[i] = 0u;

    // ---- Stage x slice: x_sm[t][b][i] ----
    for (int idx = tid; idx < BT * TLEN * 4; idx += NTH) {
        int b = idx >> 11, r = idx & 2047;
        x_sm[(r >> 2) * (BT * 4) + b * 4 + (r & 3)] = x[(b_base + b) * (TLEN * 4) + r];
    }

    // ---- Epilogue constants: thread u owns unit j, batches 2bp, 2bp+1 ----
    const int j  = tid & 127;
    const int bp = tid >> 7;
    float4 wi[4];
    float  bias[4];
    #pragma unroll
    for (int gt = 0; gt < 4; gt++) {
        int g = gt * 128 + j;
        wi[gt]   = *reinterpret_cast<const float4*>(Wih + g * 4);
        bias[gt] = bih[g] + bhh[g];
    }
    float cA = 0.f, cB = 0.f, hA = 0.f, hB = 0.f;

    const __half* hrow = h_sm + gid * HPITCH + tig * 2;   // B frag base (n=gid)
    __syncthreads();

    for (int t = 0; t < TLEN; t++) {
        const int tx = dir ? (TLEN - 1 - t) : t;

        // ---- B fragments from h_sm ----
        uint32_t b0[8], b1[8];
        #pragma unroll
        for (int kc = 0; kc < 8; kc++) {
            b0[kc] = *reinterpret_cast<const uint32_t*>(hrow + kc * 16);
            b1[kc] = *reinterpret_cast<const uint32_t*>(hrow + kc * 16 + 8);
        }

        // ---- MMA: 4 m-tiles x 8 k-chunks ----
        float acc[4][4];
        #pragma unroll
        for (int mt = 0; mt < 4; mt++) {
            acc[mt][0] = acc[mt][1] = acc[mt][2] = acc[mt][3] = 0.f;
            #pragma unroll
            for (int kc = 0; kc < 8; kc++)
                mma16816(acc[mt], A[mt][kc], b0[kc], b1[kc]);
        }

        // ---- Dump gates (cols 0-3 live in lanes tig<2) ----
        if (tig < 2) {
            #pragma unroll
            for (int mt = 0; mt < 4; mt++) {
                const int r0 = w * 64 + mt * 16 + gid;
                *reinterpret_cast<float2*>(gates_sm + r0 * GPITCH + tig * 2) =
                    make_float2(acc[mt][0], acc[mt][1]);
                *reinterpret_cast<float2*>(gates_sm + (r0 + 8) * GPITCH + tig * 2) =
                    make_float2(acc[mt][2], acc[mt][3]);
            }
        }
        __syncthreads();

        // ---- Epilogue: unit j, batches 2bp, 2bp+1 ----
        float2 gi = *reinterpret_cast<const float2*>(gates_sm + (0 * 128 + j) * GPITCH + bp * 2);
        float2 gf = *reinterpret_cast<const float2*>(gates_sm + (1 * 128 + j) * GPITCH + bp * 2);
        float2 gg = *reinterpret_cast<const float2*>(gates_sm + (2 * 128 + j) * GPITCH + bp * 2);
        float2 go = *reinterpret_cast<const float2*>(gates_sm + (3 * 128 + j) * GPITCH + bp * 2);

        const float* xr = x_sm + tx * (BT * 4) + bp * 8;
        float4 xa = *reinterpret_cast<const float4*>(xr);
        float4 xb = *reinterpret_cast<const float4*>(xr + 4);

        #pragma unroll
        for (int gt = 0; gt < 4; gt++) {
            float xwA = fmaf(xa.x, wi[gt].x, fmaf(xa.y, wi[gt].y,
                        fmaf(xa.z, wi[gt].z, fmaf(xa.w, wi[gt].w, bias[gt]))));
            float xwB = fmaf(xb.x, wi[gt].x, fmaf(xb.y, wi[gt].y,
                        fmaf(xb.z, wi[gt].z, fmaf(xb.w, wi[gt].w, bias[gt]))));
            if (gt == 0) { gi.x += xwA; gi.y += xwB; }
            if (gt == 1) { gf.x += xwA; gf.y += xwB; }
            if (gt == 2) { gg.x += xwA; gg.y += xwB; }
            if (gt == 3) { go.x += xwA; go.y += xwB; }
        }

        {
            float iv = sigmoid_f(gi.x), fv = sigmoid_f(gf.x);
            float gv = tanh_f(gg.x),    ov = sigmoid_f(go.x);
            cA = fmaf(fv, cA, iv * gv); hA = ov * tanh_f(cA);
        }
        {
            float iv = sigmoid_f(gi.y), fv = sigmoid_f(gf.y);
            float gv = tanh_f(gg.y),    ov = sigmoid_f(go.y);
            cB = fmaf(fv, cB, iv * gv); hB = ov * tanh_f(cB);
        }
        h_sm[(bp * 2 + 0) * HPITCH + j] = __float2half_rn(hA);
        h_sm[(bp * 2 + 1) * HPITCH + j] = __float2half_rn(hB);
        __syncthreads();
    }

    // ---- Output: out[b][dir*128 + j], fp32 from registers ----
    out[(b_base + bp * 2 + 0) * (2 * HD) + dir * HD + j] = hA;
    out[(b_base + bp * 2 + 1) * (2 * HD) + dir * HD + j] = hB;
}

extern "C" void kernel_launch(void* const* d_in, const int* in_sizes, int n_in,
                              void* d_out, int out_size)
{
    const float* x     = (const float*)d_in[0];
    const float* Wih_f = (const float*)d_in[1];
    const float* Whh_f = (const float*)d_in[2];
    const float* bih_f = (const float*)d_in[3];
    const float* bhh_f = (const float*)d_in[4];
    const float* Wih_b = (const float*)d_in[5];
    const float* Whh_b = (const float*)d_in[6];
    const float* bih_b = (const float*)d_in[7];
    const float* bhh_b = (const float*)d_in[8];
    float* out = (float*)d_out;

    cudaFuncSetAttribute(lstm_mma_kernel,
                         cudaFuncAttributeMaxDynamicSharedMemorySize, SM_TOTAL);

    lstm_mma_kernel<<<128, NTH, SM_TOTAL>>>(
        x, Wih_f, Whh_f, bih_f, bhh_f, Wih_b, Whh_b, bih_b, bhh_b, out);
}

// round 12
// speedup vs baseline: 1.0069x; 1.0009x over previous
#include <cuda_runtime.h>
#include <cuda_fp16.h>
#include <cstdint>

// Bidirectional LSTM (H=128, I=4, B=256, T=512), final h only. out [B,2H] fp32.
// Grid: 128 CTAs = 2 dirs x 64 batch-tiles (BT=4), 256 threads (8 warps).
// Weight-stationary register MMA: warp w holds Whh rows [w*64,(w+1)*64) as
// m16n8k16 A fragments in registers (loaded once). Per step:
//   gates[512,8] = Whh_fp16 @ h_fp16^T  (N=8: batches 0-3 real, 4-7 zero)
// via 4 m-tiles x 8 k-chunks of mma.sync.m16n8k16.f32.f16.f16.f32 per warp.
// Epilogue: thread u owns unit j=u&127, batches 2bp,2bp+1 (bp=u>>7); fp32 xw,
// accurate exp-based activations, fp32 c/h; h -> fp16 -> B buffer in SMEM.

#define HD     128
#define TLEN   512
#define BT     4
#define NTH    256
#define GPITCH 10        // gates row pitch in floats (40 B)
#define HPITCH 136       // h row pitch in halves (272 B, conflict-free)

// dynamic SMEM layout (bytes)
#define SM_GATES  0
#define GATES_B   (512 * GPITCH * 4)            // 20480
#define SM_H      GATES_B                        // 20480
#define H_B       (8 * HPITCH * 2)               // 2176
#define SM_X      (SM_GATES + GATES_B + H_B)     // 22656
#define X_B       (TLEN * BT * 4 * 4)            // 32768
#define SM_TOTAL  (SM_X + X_B)                   // 55424

__device__ __forceinline__ void mma16816(float* d, const uint32_t* a,
                                         uint32_t b0, uint32_t b1) {
    asm volatile(
        "mma.sync.aligned.m16n8k16.row.col.f32.f16.f16.f32 "
        "{%0,%1,%2,%3}, {%4,%5,%6,%7}, {%8,%9}, {%0,%1,%2,%3};"
        : "+f"(d[0]), "+f"(d[1]), "+f"(d[2]), "+f"(d[3])
        : "r"(a[0]), "r"(a[1]), "r"(a[2]), "r"(a[3]), "r"(b0), "r"(b1));
}

__device__ __forceinline__ uint32_t packh2(float lo, float hi) {
    __half2 h = __floats2half2_rn(lo, hi);
    return *reinterpret_cast<uint32_t*>(&h);
}
__device__ __forceinline__ float sigmoid_f(float x) {
    float e = __expf(-x);
    return __fdividef(1.0f, 1.0f + e);
}
__device__ __forceinline__ float tanh_f(float x) {
    float ax = fabsf(x);
    float e = __expf(-2.0f * ax);
    float t = __fdividef(1.0f - e, 1.0f + e);
    return copysignf(t, x);
}

__global__ void __launch_bounds__(NTH, 1)
lstm_mma_kernel(const float* __restrict__ x,
                const float* __restrict__ Wih_f, const float* __restrict__ Whh_f,
                const float* __restrict__ bih_f, const float* __restrict__ bhh_f,
                const float* __restrict__ Wih_b, const float* __restrict__ Whh_b,
                const float* __restrict__ bih_b, const float* __restrict__ bhh_b,
                float* __restrict__ out)
{
    extern __shared__ unsigned char smem[];
    float*  gates_sm = reinterpret_cast<float*>(smem + SM_GATES);
    __half* h_sm     = reinterpret_cast<__half*>(smem + SM_H);
    float*  x_sm     = reinterpret_cast<float*>(smem + SM_X);

    const int tid = threadIdx.x;
    const int w   = tid >> 5;          // warp 0..7
    const int l   = tid & 31;
    const int gid = l >> 2;            // 0..7
    const int tig = l & 3;             // 0..3
    const int bx  = blockIdx.x;
    const int dir = bx >> 6;
    const int b_base = (bx & 63) * BT;

    const float* Wih = dir ? Wih_b : Wih_f;
    const float* Whh = dir ? Whh_b : Whh_f;
    const float* bih = dir ? bih_b : bih_f;
    const float* bhh = dir ? bhh_b : bhh_f;

    // ---- Load stationary A fragments: warp w owns rows [w*64, w*64+64) ----
    // a[mt][kc][0..3]: rows (r0, r0+8) x k (k0,k0+1, k0+8,k0+9), r0=w*64+mt*16+gid
    uint32_t A[4][8][4];
    #pragma unroll
    for (int mt = 0; mt < 4; mt++) {
        const int r0 = w * 64 + mt * 16 + gid;
        const float* row0 = Whh + r0 * HD;
        const float* row1 = Whh + (r0 + 8) * HD;
        #pragma unroll
        for (int kc = 0; kc < 8; kc++) {
            const int k0 = kc * 16 + tig * 2;
            float2 p00 = *reinterpret_cast<const float2*>(row0 + k0);
            float2 p10 = *reinterpret_cast<const float2*>(row1 + k0);
            float2 p01 = *reinterpret_cast<const float2*>(row0 + k0 + 8);
            float2 p11 = *reinterpret_cast<const float2*>(row1 + k0 + 8);
            A[mt][kc][0] = packh2(p00.x, p00.y);
            A[mt][kc][1] = packh2(p10.x, p10.y);
            A[mt][kc][2] = packh2(p01.x, p01.y);
            A[mt][kc][3] = packh2(p11.x, p11.y);
        }
    }

    // ---- Zero h buffer (8 rows x HPITCH halves; rows 4-7 stay zero) ----
    for (int i = tid; i < (8 * HPITCH) / 2; i += NTH)
        reinterpret_cast<uint32_t*>(h_sm)[i] = 0u;

    // ---- Stage x slice: x_sm[t][b][i] ----
    for (int idx = tid; idx < BT * TLEN * 4; idx += NTH) {
        int b = idx >> 11, r = idx & 2047;
        x_sm[(r >> 2) * (BT * 4) + b * 4 + (r & 3)] = x[(b_base + b) * (TLEN * 4) + r];
    }

    // ---- Epilogue constants: thread u owns unit j, batches 2bp, 2bp+1 ----
    const int j  = tid & 127;
    const int bp = tid >> 7;
    float4 wi[4];
    float  bias[4];
    #pragma unroll
    for (int gt = 0; gt < 4; gt++) {
        int g = gt * 128 + j;
        wi[gt]   = *reinterpret_cast<const float4*>(Wih + g * 4);
        bias[gt] = bih[g] + bhh[g];
    }
    float cA = 0.f, cB = 0.f, hA = 0.f, hB = 0.f;

    const __half* hrow = h_sm + gid * HPITCH + tig * 2;   // B frag base (n=gid)
    __syncthreads();

    for (int t = 0; t < TLEN; t++) {
        const int tx = dir ? (TLEN - 1 - t) : t;

        // ---- B fragments from h_sm ----
        uint32_t b0[8], b1[8];
        #pragma unroll
        for (int kc = 0; kc < 8; kc++) {
            b0[kc] = *reinterpret_cast<const uint32_t*>(hrow + kc * 16);
            b1[kc] = *reinterpret_cast<const uint32_t*>(hrow + kc * 16 + 8);
        }

        // ---- MMA: 4 m-tiles x 8 k-chunks ----
        float acc[4][4];
        #pragma unroll
        for (int mt = 0; mt < 4; mt++) {
            acc[mt][0] = acc[mt][1] = acc[mt][2] = acc[mt][3] = 0.f;
            #pragma unroll
            for (int kc = 0; kc < 8; kc++)
                mma16816(acc[mt], A[mt][kc], b0[kc], b1[kc]);
        }

        // ---- Dump gates (cols 0-3 live in lanes tig<2) ----
        if (tig < 2) {
            #pragma unroll
            for (int mt = 0; mt < 4; mt++) {
                const int r0 = w * 64 + mt * 16 + gid;
                *reinterpret_cast<float2*>(gates_sm + r0 * GPITCH + tig * 2) =
                    make_float2(acc[mt][0], acc[mt][1]);
                *reinterpret_cast<float2*>(gates_sm + (r0 + 8) * GPITCH + tig * 2) =
                    make_float2(acc[mt][2], acc[mt][3]);
            }
        }
        __syncthreads();

        // ---- Epilogue: unit j, batches 2bp, 2bp+1 ----
        float2 gi = *reinterpret_cast<const float2*>(gates_sm + (0 * 128 + j) * GPITCH + bp * 2);
        float2 gf = *reinterpret_cast<const float2*>(gates_sm + (1 * 128 + j) * GPITCH + bp * 2);
        float2 gg = *reinterpret_cast<const float2*>(gates_sm + (2 * 128 + j) * GPITCH + bp * 2);
        float2 go = *reinterpret_cast<const float2*>(gates_sm + (3 * 128 + j) * GPITCH + bp * 2);

        const float* xr = x_sm + tx * (BT * 4) + bp * 8;
        float4 xa = *reinterpret_cast<const float4*>(xr);
        float4 xb = *reinterpret_cast<const float4*>(xr + 4);

        #pragma unroll
        for (int gt = 0; gt < 4; gt++) {
            float xwA = fmaf(xa.x, wi[gt].x, fmaf(xa.y, wi[gt].y,
                        fmaf(xa.z, wi[gt].z, fmaf(xa.w, wi[gt].w, bias[gt]))));
            float xwB = fmaf(xb.x, wi[gt].x, fmaf(xb.y, wi[gt].y,
                        fmaf(xb.z, wi[gt].z, fmaf(xb.w, wi[gt].w, bias[gt]))));
            if (gt == 0) { gi.x += xwA; gi.y += xwB; }
            if (gt == 1) { gf.x += xwA; gf.y += xwB; }
            if (gt == 2) { gg.x += xwA; gg.y += xwB; }
            if (gt == 3) { go.x += xwA; go.y += xwB; }
        }

        {
            float iv = sigmoid_f(gi.x), fv = sigmoid_f(gf.x);
            float gv = tanh_f(gg.x),    ov = sigmoid_f(go.x);
            cA = fmaf(fv, cA, iv * gv); hA = ov * tanh_f(cA);
        }
        {
            float iv = sigmoid_f(gi.y), fv = sigmoid_f(gf.y);
            float gv = tanh_f(gg.y),    ov = sigmoid_f(go.y);
            cB = fmaf(fv, cB, iv * gv); hB = ov * tanh_f(cB);
        }
        h_sm[(bp * 2 + 0) * HPITCH + j] = __float2half_rn(hA);
        h_sm[(bp * 2 + 1) * HPITCH + j] = __float2half_rn(hB);
        __syncthreads();
    }

    // ---- Output: out[b][dir*128 + j], fp32 from registers ----
    out[(b_base + bp * 2 + 0) * (2 * HD) + dir * HD + j] = hA;
    out[(b_base + bp * 2 + 1) * (2 * HD) + dir * HD + j] = hB;
}

extern "C" void kernel_launch(void* const* d_in, const int* in_sizes, int n_in,
                              void* d_out, int out_size)
{
    const float* x     = (const float*)d_in[0];
    const float* Wih_f = (const float*)d_in[1];
    const float* Whh_f = (const float*)d_in[2];
    const float* bih_f = (const float*)d_in[3];
    const float* bhh_f = (const float*)d_in[4];
    const float* Wih_b = (const float*)d_in[5];
    const float* Whh_b = (const float*)d_in[6];
    const float* bih_b = (const float*)d_in[7];
    const float* bhh_b = (const float*)d_in[8];
    float* out = (float*)d_out;

    cudaFuncSetAttribute(lstm_mma_kernel,
                         cudaFuncAttributeMaxDynamicSharedMemorySize, SM_TOTAL);

    lstm_mma_kernel<<<128, NTH, SM_TOTAL>>>(
        x, Wih_f, Whh_f, bih_f, bhh_f, Wih_b, Whh_b, bih_b, bhh_b, out);
}